// round 17
// baseline (speedup 1.0000x reference)
#include <cuda_runtime.h>
#include <cuda_fp16.h>
#include <cstdint>

#define NODES 50000
#define EDGES 800000
#define HID   128
#define CAP   128
#define OVFMAX 65536
#define NT64    782           // ceil(50000/64)

// ---------------------------------------------------------------------------
// Device-global scratch (no allocations allowed)
// ---------------------------------------------------------------------------
__device__ __half g_P[(size_t)NODES * HID];
__device__ __half g_Q[(size_t)NODES * HID];
__device__ int    g_cnt[NODES];
__device__ int    g_bucket[(size_t)NODES * CAP];
__device__ int2   g_ovf[OVFMAX];
__device__ int    g_novf;

// fp16 images: per 64-row tile, 16 KB contiguous; element (r,k) at byte
// off = r*256 + ((k>>6)<<7) + (((k&63)<<1) ^ ((r&7)<<4)).
__device__ uint4 g_hF[(size_t)NT64 * 1024];
__device__ uint4 g_sF[(size_t)NT64 * 1024];

// Weight images (transposed, single fp16). W1: [W1a 32KB][W1b 32KB].
__device__ uint4 g_iWin[2048];
__device__ uint4 g_iW1s[4096];
__device__ uint4 g_iW2 [2048];

// ---------------------------------------------------------------------------
__device__ __forceinline__ uint32_t smem_u32(const void* p) {
    uint32_t a;
    asm("{ .reg .u64 t; cvta.to.shared.u64 t, %1; cvt.u32.u64 %0, t; }"
        : "=r"(a) : "l"(p));
    return a;
}
__device__ __forceinline__ unsigned packh2(float x, float y) {
    __half2 t = __floats2half2_rn(x, y);
    return *reinterpret_cast<unsigned*>(&t);
}
__device__ __forceinline__ void ldsm4(unsigned* r, uint32_t addr) {
    asm volatile("ldmatrix.sync.aligned.m8n8.x4.shared.b16 {%0,%1,%2,%3}, [%4];"
                 : "=r"(r[0]), "=r"(r[1]), "=r"(r[2]), "=r"(r[3]) : "r"(addr));
}
__device__ __forceinline__ void mmah(float* d, const unsigned* a,
                                     unsigned b0, unsigned b1) {
    asm volatile(
        "mma.sync.aligned.m16n8k16.row.col.f32.f16.f16.f32 "
        "{%0,%1,%2,%3},{%4,%5,%6,%7},{%8,%9},{%0,%1,%2,%3};"
        : "+f"(d[0]), "+f"(d[1]), "+f"(d[2]), "+f"(d[3])
        : "r"(a[0]), "r"(a[1]), "r"(a[2]), "r"(a[3]), "r"(b0), "r"(b1));
}
__device__ __forceinline__ void cpa16(uint32_t dst, const void* src) {
    asm volatile("cp.async.cg.shared.global [%0], [%1], 16;"
                 :: "r"(dst), "l"(src));
}
__device__ __forceinline__ void cpa16z(uint32_t dst, const void* src, int sz) {
    asm volatile("cp.async.cg.shared.global [%0], [%1], 16, %2;"
                 :: "r"(dst), "l"(src), "r"(sz));
}
#define CP_COMMIT() asm volatile("cp.async.commit_group;" ::: "memory")
#define CP_WAIT0()  asm volatile("cp.async.wait_group 0;" ::: "memory")

__device__ __forceinline__ uint32_t img_off(int r, int k) {
    return (uint32_t)r * 256 + ((k >> 6) << 7) + ((((k & 63) << 1)) ^ ((r & 7) << 4));
}
__device__ __forceinline__ uint32_t f32_off(int r, int cc) {
    return (uint32_t)r * 512 +
           (((uint32_t)cc * 16) ^ ((r & 7) << 4) ^ ((cc >> 3) << 4));
}

// ---------------------------------------------------------------------------
// Prep: single-fp16 weight images + zero counters
// ---------------------------------------------------------------------------
__device__ __forceinline__ void img_write_s(uint4* img, int blk, int n, int k,
                                            float v) {
    __half* p = (__half*)img + blk * 128 * 128;
    p[img_off(n, k) >> 1] = __float2half_rn(v);
}

__global__ void __launch_bounds__(256)
prep_kernel(const float* __restrict__ W_in, const float* __restrict__ W1,
            const float* __restrict__ W2)
{
    int idx = blockIdx.x * blockDim.x + threadIdx.x;
    int n = (idx >> 7) & 127, k = idx & 127;
    if (idx < 16384) {
        img_write_s(g_iWin, 0, n, k, W_in[k * 128 + n]);
    } else if (idx < 32768) {
        img_write_s(g_iW1s, 0, n, k, W1[k * 128 + n]);
    } else if (idx < 49152) {
        img_write_s(g_iW1s, 1, n, k, W1[(128 + k) * 128 + n]);
    } else if (idx < 65536) {
        img_write_s(g_iW2, 0, n, k, W2[k * 128 + n]);
    }
    if (idx < NODES) g_cnt[idx] = 0;
    if (idx == 0) g_novf = 0;
}

// ---------------------------------------------------------------------------
// Single-fp16 mainloop: per k-step 4 ldsm4, 8 HMMAs. 8 warps, 64x128 tile.
// ---------------------------------------------------------------------------
__device__ __forceinline__ void tile_ml16s(
    float acc[2][4][4], uint32_t aImg, uint32_t bImg,
    int warpM, int warpN, int fi, int fswz, int fk8)
{
#pragma unroll
    for (int mt = 0; mt < 2; ++mt)
#pragma unroll
        for (int ns = 0; ns < 4; ++ns)
#pragma unroll
            for (int e = 0; e < 4; ++e) acc[mt][ns][e] = 0.f;

#pragma unroll
    for (int ks = 0; ks < 8; ++ks) {
        const int k8 = ks * 16 + fk8;
        const uint32_t koff = ((k8 >> 6) << 7) + (((k8 & 63) << 1) ^ fswz);
        unsigned a[2][4], b[2][4];
#pragma unroll
        for (int mt = 0; mt < 2; ++mt)
            ldsm4(a[mt], aImg + (uint32_t)(warpM * 32 + mt * 16 + fi) * 256 + koff);
#pragma unroll
        for (int nt = 0; nt < 2; ++nt)
            ldsm4(b[nt], bImg + (uint32_t)(warpN * 32 + nt * 16 + fi) * 256 + koff);
#pragma unroll
        for (int mt = 0; mt < 2; ++mt)
#pragma unroll
            for (int nt = 0; nt < 2; ++nt) {
                mmah(acc[mt][nt * 2],     a[mt], b[nt][0], b[nt][2]);
                mmah(acc[mt][nt * 2 + 1], a[mt], b[nt][1], b[nt][3]);
            }
    }
}

// ---------------------------------------------------------------------------
// gemm_xa: fp32 x (64-row tiles) via cp.async; convert to fp16 image in smem;
// mainloop; epilogue -> relu+bias -> gmem fp16 image.
// smem: [buf 32K][W 32K] = 64 KB -> 2 CTAs/SM.
// ---------------------------------------------------------------------------
__global__ void __launch_bounds__(256, 2)
gemm_xa(const float* __restrict__ A, const uint4* __restrict__ Wimg,
        const float* __restrict__ bias, uint4* __restrict__ outF,
        int M, int ntiles)
{
    extern __shared__ char smem[];
    const uint32_t sb = smem_u32(smem);
    const uint32_t sW = sb + 32768;

    const int tid = threadIdx.x;
    const int wid = tid >> 5;
    const int L   = tid & 31;
    const int warpM = wid >> 2, warpN = wid & 3;
    const int fi = L & 15, fswz = (fi & 7) << 4, fk8 = (L >> 4) * 8;
    const int sr = tid >> 2, sq = tid & 3;

    for (int i = tid; i < 2048; i += 256) cpa16(sW + i * 16, Wimg + i);
    {
        int m0 = blockIdx.x * 64;
        for (int i = tid; i < 2048; i += 256) {
            int r = i >> 5, cc = i & 31;
            int gr = m0 + r;
            int sz = (gr < M) ? 16 : 0;
            const float* src = A + (size_t)(gr < M ? gr : 0) * 128 + cc * 4;
            cpa16z(sb + f32_off(r, cc), src, sz);
        }
    }
    CP_COMMIT();

    for (int tile = blockIdx.x; tile < ntiles; tile += gridDim.x) {
        CP_WAIT0();
        __syncthreads();

        float4 v[8];
#pragma unroll
        for (int j = 0; j < 8; ++j)
            v[j] = *(const float4*)(smem + f32_off(sr, sq * 8 + j));
        __syncthreads();

#pragma unroll
        for (int j = 0; j < 8; ++j) {
            float4 a = v[j];
            uint32_t off = img_off(sr, (sq * 8 + j) * 4);
            *(uint2*)(smem + off) =
                make_uint2(packh2(a.x, a.y), packh2(a.z, a.w));
        }
        __syncthreads();

        float acc[2][4][4];
        tile_ml16s(acc, sb, sW, warpM, warpN, fi, fswz, fk8);

        const int m0 = tile * 64;
        char* fB = (char*)outF + (size_t)tile * 16384;
#pragma unroll
        for (int mt = 0; mt < 2; ++mt) {
            int r0 = warpM * 32 + mt * 16 + (L >> 2);
            int r1 = r0 + 8;
#pragma unroll
            for (int ns = 0; ns < 4; ++ns) {
                int c = warpN * 32 + ns * 8 + (L & 3) * 2;
                float b0 = bias[c], b1 = bias[c + 1];
                float v00 = fmaxf(acc[mt][ns][0] + b0, 0.f);
                float v01 = fmaxf(acc[mt][ns][1] + b1, 0.f);
                float v10 = fmaxf(acc[mt][ns][2] + b0, 0.f);
                float v11 = fmaxf(acc[mt][ns][3] + b1, 0.f);
                if (m0 + r0 < M)
                    *(unsigned*)(fB + img_off(r0, c)) = packh2(v00, v01);
                if (m0 + r1 < M)
                    *(unsigned*)(fB + img_off(r1, c)) = packh2(v10, v11);
            }
        }
        __syncthreads();

        int nxt = tile + gridDim.x;
        if (nxt < ntiles) {
            int m0n = nxt * 64;
            for (int i = tid; i < 2048; i += 256) {
                int r = i >> 5, cc = i & 31;
                int gr = m0n + r;
                int sz = (gr < M) ? 16 : 0;
                const float* src = A + (size_t)(gr < M ? gr : 0) * 128 + cc * 4;
                cpa16z(sb + f32_off(r, cc), src, sz);
            }
        }
        CP_COMMIT();
    }
}

// ---------------------------------------------------------------------------
// gemm_pq: one A pass -> P (fp16, +b1), Q (fp16).
// smem: [A0 16K][A1 16K][W1a 32K|W1b 32K] = 96 KB -> 2 CTAs/SM.
// ---------------------------------------------------------------------------
__global__ void __launch_bounds__(256, 2)
gemm_pq(const uint4* __restrict__ aImgG, const uint4* __restrict__ Wab,
        const float* __restrict__ b1, __half* __restrict__ P,
        __half* __restrict__ Q, int M, int ntiles)
{
    extern __shared__ char smem[];
    const uint32_t sb = smem_u32(smem);
    const uint32_t sW = sb + 32768;

    const int tid = threadIdx.x;
    const int wid = tid >> 5;
    const int L   = tid & 31;
    const int warpM = wid >> 2, warpN = wid & 3;
    const int fi = L & 15, fswz = (fi & 7) << 4, fk8 = (L >> 4) * 8;

    for (int i = tid; i < 4096; i += 256) cpa16(sW + i * 16, Wab + i);
    {
        const uint4* srcA = aImgG + (size_t)blockIdx.x * 1024;
        for (int i = tid; i < 1024; i += 256) cpa16(sb + i * 16, srcA + i);
    }
    CP_COMMIT();

    int cur = 0;
    for (int tile = blockIdx.x; tile < ntiles; tile += gridDim.x) {
        CP_WAIT0();
        __syncthreads();

        int nxt = tile + gridDim.x;
        if (nxt < ntiles) {
            uint32_t dst = sb + (cur ^ 1) * 16384;
            const uint4* srcA = aImgG + (size_t)nxt * 1024;
            for (int i = tid; i < 1024; i += 256) cpa16(dst + i * 16, srcA + i);
        }
        CP_COMMIT();

        const uint32_t sA = sb + cur * 16384;
        const int m0 = tile * 64;
        float acc[2][4][4];

        // P = h @ W1a + b1 (fp16)
        tile_ml16s(acc, sA, sW, warpM, warpN, fi, fswz, fk8);
#pragma unroll
        for (int mt = 0; mt < 2; ++mt) {
            int gr0 = m0 + warpM * 32 + mt * 16 + (L >> 2);
            int gr1 = gr0 + 8;
#pragma unroll
            for (int ns = 0; ns < 4; ++ns) {
                int c = warpN * 32 + ns * 8 + (L & 3) * 2;
                float b0 = b1[c], bb1 = b1[c + 1];
                if (gr0 < M)
                    *(unsigned*)(P + (size_t)gr0 * 128 + c) =
                        packh2(acc[mt][ns][0] + b0, acc[mt][ns][1] + bb1);
                if (gr1 < M)
                    *(unsigned*)(P + (size_t)gr1 * 128 + c) =
                        packh2(acc[mt][ns][2] + b0, acc[mt][ns][3] + bb1);
            }
        }

        // Q = h @ W1b (fp16)
        tile_ml16s(acc, sA, sW + 32768, warpM, warpN, fi, fswz, fk8);
#pragma unroll
        for (int mt = 0; mt < 2; ++mt) {
            int gr0 = m0 + warpM * 32 + mt * 16 + (L >> 2);
            int gr1 = gr0 + 8;
#pragma unroll
            for (int ns = 0; ns < 4; ++ns) {
                int c = warpN * 32 + ns * 8 + (L & 3) * 2;
                if (gr0 < M)
                    *(unsigned*)(Q + (size_t)gr0 * 128 + c) =
                        packh2(acc[mt][ns][0], acc[mt][ns][1]);
                if (gr1 < M)
                    *(unsigned*)(Q + (size_t)gr1 * 128 + c) =
                        packh2(acc[mt][ns][2], acc[mt][ns][3]);
            }
        }
        cur ^= 1;
    }
}

// ---------------------------------------------------------------------------
// gemm_s2o: S image @ W2 -> relu(.+deg*b2) -> @Wc + bc -> out.
// smem: [A0 16K][A1 16K][W 32K][sOut 512B] -> 2 CTAs/SM.
// ---------------------------------------------------------------------------
__global__ void __launch_bounds__(256, 2)
gemm_s2o(const uint4* __restrict__ aImgG, const uint4* __restrict__ Wimg,
         const float* __restrict__ b2, const int* __restrict__ rowcnt,
         const float* __restrict__ Wc, const float* __restrict__ bc,
         float* __restrict__ out, int M, int ntiles)
{
    extern __shared__ char smem[];
    const uint32_t sb = smem_u32(smem);
    const uint32_t sW = sb + 32768;
    float* sOut = (float*)(smem + 65536);

    const int tid = threadIdx.x;
    const int wid = tid >> 5;
    const int L   = tid & 31;
    const int warpM = wid >> 2, warpN = wid & 3;
    const int fi = L & 15, fswz = (fi & 7) << 4, fk8 = (L >> 4) * 8;

    for (int i = tid; i < 2048; i += 256) cpa16(sW + i * 16, Wimg + i);
    {
        int t0 = blockIdx.x;
        if (t0 < ntiles) {
            const uint4* srcA = aImgG + (size_t)t0 * 1024;
            for (int i = tid; i < 1024; i += 256) cpa16(sb + i * 16, srcA + i);
        }
    }
    CP_COMMIT();

    int cur = 0;
    for (int tile = blockIdx.x; tile < ntiles; tile += gridDim.x) {
        CP_WAIT0();
        __syncthreads();

        int nxt = tile + gridDim.x;
        if (nxt < ntiles) {
            uint32_t dst = sb + (cur ^ 1) * 16384;
            const uint4* srcA = aImgG + (size_t)nxt * 1024;
            for (int i = tid; i < 1024; i += 256) cpa16(dst + i * 16, srcA + i);
        }
        CP_COMMIT();

        float acc[2][4][4];
        tile_ml16s(acc, sb + cur * 16384, sW, warpM, warpN, fi, fswz, fk8);

        if (tid < 128) sOut[tid] = 0.f;
        __syncthreads();

        const int m0 = tile * 64;
#pragma unroll
        for (int mt = 0; mt < 2; ++mt) {
            int gr0 = m0 + warpM * 32 + mt * 16 + (L >> 2);
            int gr1 = gr0 + 8;
            float sc0 = (gr0 < M) ? (float)rowcnt[gr0] : 0.f;
            float sc1 = (gr1 < M) ? (float)rowcnt[gr1] : 0.f;
            float p00 = 0.f, p01 = 0.f, p10 = 0.f, p11 = 0.f;
#pragma unroll
            for (int ns = 0; ns < 4; ++ns) {
                int c = warpN * 32 + ns * 8 + (L & 3) * 2;
                float b0 = b2[c], b1 = b2[c + 1];
                float v00 = fmaxf(acc[mt][ns][0] + sc0 * b0, 0.f);
                float v01 = fmaxf(acc[mt][ns][1] + sc0 * b1, 0.f);
                float v10 = fmaxf(acc[mt][ns][2] + sc1 * b0, 0.f);
                float v11 = fmaxf(acc[mt][ns][3] + sc1 * b1, 0.f);
                float2 w0 = *(const float2*)(Wc + c * 2);
                float2 w1 = *(const float2*)(Wc + (c + 1) * 2);
                p00 += v00 * w0.x + v01 * w1.x;
                p01 += v00 * w0.y + v01 * w1.y;
                p10 += v10 * w0.x + v11 * w1.x;
                p11 += v10 * w0.y + v11 * w1.y;
            }
#pragma unroll
            for (int off = 1; off <= 2; off <<= 1) {
                p00 += __shfl_xor_sync(0xffffffffu, p00, off);
                p01 += __shfl_xor_sync(0xffffffffu, p01, off);
                p10 += __shfl_xor_sync(0xffffffffu, p10, off);
                p11 += __shfl_xor_sync(0xffffffffu, p11, off);
            }
            if ((L & 3) == 0) {
                int r0 = warpM * 32 + mt * 16 + (L >> 2);
                atomicAdd(&sOut[r0 * 2],           p00);
                atomicAdd(&sOut[r0 * 2 + 1],       p01);
                atomicAdd(&sOut[(r0 + 8) * 2],     p10);
                atomicAdd(&sOut[(r0 + 8) * 2 + 1], p11);
            }
        }
        __syncthreads();

        if (tid < 128) {
            int r = tid >> 1, k = tid & 1;
            int gr = m0 + r;
            if (gr < M) out[(size_t)gr * 2 + k] = sOut[tid] + bc[k];
        }
        cur ^= 1;
    }
}

// ---------------------------------------------------------------------------
__global__ void __launch_bounds__(256)
bucket_kernel(const int* __restrict__ ei)
{
    int e = blockIdx.x * blockDim.x + threadIdx.x;
    if (e >= EDGES) return;
    int s = ei[e];
    int d = ei[EDGES + e];
    int slot = atomicAdd(&g_cnt[d], 1);
    if (slot < CAP) {
        g_bucket[(size_t)d * CAP + slot] = s;
    } else {
        int o = atomicAdd(&g_novf, 1);
        if (o < OVFMAX) g_ovf[o] = make_int2(s, d);
    }
}

// Warp per node: S[d] = sum relu(P[d]+Q[src]); P/Q fp16; MLP-8 gather batches.
__global__ void __launch_bounds__(256)
node_kernel()
{
    int d    = (blockIdx.x * blockDim.x + threadIdx.x) >> 5;
    int lane = threadIdx.x & 31;
    if (d >= NODES) return;

    int n = g_cnt[d];
    if (n > CAP) n = CAP;

    uint2 praw = ((const uint2*)(g_P + (size_t)d * HID))[lane];
    float2 p0 = __half22float2(*(__half2*)&praw.x);
    float2 p1 = __half22float2(*(__half2*)&praw.y);
    float4 acc = make_float4(0.f, 0.f, 0.f, 0.f);
    const int* bkt = g_bucket + (size_t)d * CAP;

    for (int i0 = 0; i0 < n; i0 += 8) {
        int lim = n - i0;
        int idxs[8];
        uint2 q[8];
#pragma unroll
        for (int u = 0; u < 8; ++u)
            idxs[u] = (u < lim) ? __ldg(bkt + i0 + u) : idxs[0];
#pragma unroll
        for (int u = 0; u < 8; ++u)
            if (u < lim)
                q[u] = ((const uint2*)(g_Q + (size_t)idxs[u] * HID))[lane];
#pragma unroll
        for (int u = 0; u < 8; ++u) {
            if (u < lim) {
                float2 f0 = __half22float2(*(__half2*)&q[u].x);
                float2 f1 = __half22float2(*(__half2*)&q[u].y);
                acc.x += fmaxf(p0.x + f0.x, 0.f);
                acc.y += fmaxf(p0.y + f0.y, 0.f);
                acc.z += fmaxf(p1.x + f1.x, 0.f);
                acc.w += fmaxf(p1.y + f1.y, 0.f);
            }
        }
    }
    int r = d & 63;
    char* base = (char*)g_sF + (size_t)(d >> 6) * 16384;
    *(uint2*)(base + img_off(r, lane * 4)) =
        make_uint2(packh2(acc.x, acc.y), packh2(acc.z, acc.w));
}

// Serial overflow fixup (single warp; expected empty). RMW on S image.
__global__ void __launch_bounds__(32)
fixup_kernel()
{
    int total = g_novf;
    if (total > OVFMAX) total = OVFMAX;
    int lane = threadIdx.x;
    for (int j = 0; j < total; ++j) {
        int2 e = g_ovf[j];
        uint2 praw = ((const uint2*)(g_P + (size_t)e.y * HID))[lane];
        float2 p0 = __half22float2(*(__half2*)&praw.x);
        float2 p1 = __half22float2(*(__half2*)&praw.y);
        uint2 qraw = ((const uint2*)(g_Q + (size_t)e.x * HID))[lane];
        float2 f0 = __half22float2(*(__half2*)&qraw.x);
        float2 f1 = __half22float2(*(__half2*)&qraw.y);
        int r = e.y & 63;
        char* base = (char*)g_sF + (size_t)(e.y >> 6) * 16384;
        uint2 sv = *(uint2*)(base + img_off(r, lane * 4));
        float2 s0 = __half22float2(*(__half2*)&sv.x);
        float2 s1 = __half22float2(*(__half2*)&sv.y);
        float vx = s0.x + fmaxf(p0.x + f0.x, 0.f);
        float vy = s0.y + fmaxf(p0.y + f0.y, 0.f);
        float vz = s1.x + fmaxf(p1.x + f1.x, 0.f);
        float vw = s1.y + fmaxf(p1.y + f1.y, 0.f);
        *(uint2*)(base + img_off(r, lane * 4)) =
            make_uint2(packh2(vx, vy), packh2(vz, vw));
        __syncwarp();
    }
}

// ---------------------------------------------------------------------------
extern "C" void kernel_launch(void* const* d_in, const int* in_sizes, int n_in,
                              void* d_out, int out_size)
{
    const float* x    = (const float*)d_in[0];
    const int*   ei   = (const int*)d_in[1];
    const float* W_in = (const float*)d_in[2];
    const float* b_in = (const float*)d_in[3];
    const float* W1   = (const float*)d_in[4];
    const float* b1   = (const float*)d_in[5];
    const float* W2   = (const float*)d_in[6];
    const float* b2   = (const float*)d_in[7];
    const float* Wc   = (const float*)d_in[8];
    const float* bc   = (const float*)d_in[9];
    float*       out  = (float*)d_out;

    void *pP, *pQ, *pcnt, *pWin, *pW1s, *pW2, *phF, *psF;
    cudaGetSymbolAddress(&pP,   g_P);
    cudaGetSymbolAddress(&pQ,   g_Q);
    cudaGetSymbolAddress(&pcnt, g_cnt);
    cudaGetSymbolAddress(&pWin, g_iWin);
    cudaGetSymbolAddress(&pW1s, g_iW1s);
    cudaGetSymbolAddress(&pW2,  g_iW2);
    cudaGetSymbolAddress(&phF,  g_hF);
    cudaGetSymbolAddress(&psF,  g_sF);

    const int SMEM_XA = 64 * 1024;
    const int SMEM_PQ = 96 * 1024;
    const int SMEM_O  = 64 * 1024 + 1024;
    cudaFuncSetAttribute(gemm_xa, cudaFuncAttributeMaxDynamicSharedMemorySize, SMEM_XA);
    cudaFuncSetAttribute(gemm_pq, cudaFuncAttributeMaxDynamicSharedMemorySize, SMEM_PQ);
    cudaFuncSetAttribute(gemm_s2o, cudaFuncAttributeMaxDynamicSharedMemorySize, SMEM_O);

    const int M = NODES;
    const int GRID = 296;

    prep_kernel<<<256, 256>>>(W_in, W1, W2);
    bucket_kernel<<<(EDGES + 255) / 256, 256>>>(ei);

    // 1) h image (fp16) = relu(x @ Win + b_in)
    gemm_xa<<<GRID, 256, SMEM_XA>>>(x, (const uint4*)pWin, b_in,
                                    (uint4*)phF, M, NT64);
    // 2) P = h @ W1a + b1 ; Q = h @ W1b  (both fp16, one A pass)
    gemm_pq<<<GRID, 256, SMEM_PQ>>>((const uint4*)phF, (const uint4*)pW1s, b1,
                                    (__half*)pP, (__half*)pQ, M, NT64);
    // 3) S image (fp16) = sum_e relu(P[d]+Q[s])
    node_kernel<<<(NODES * 32 + 255) / 256, 256>>>();
    fixup_kernel<<<1, 32>>>();
    // 4+5) out = relu(S @ W2 + deg*b2) @ Wc + bc   (fused)
    gemm_s2o<<<GRID, 256, SMEM_O>>>((const uint4*)psF, (const uint4*)pW2,
                                    b2, (const int*)pcnt, Wc, bc, out, M, NT64);
}